// round 4
// baseline (speedup 1.0000x reference)
#include <cuda_runtime.h>
#include <cstdint>

#define CIN   64
#define COUT  64
#define HD    128
#define WD    128
#define BD    4
#define KK    9
#define HW    (HD*WD)

// ------------------------- scratch (device globals) -------------------------
__device__ float  g_xhwc[BD*HW*CIN];          // x in NHWC              (16 MB)
__device__ float2 g_wd2 [CIN*KK*COUT];        // w_def [c][k][o] as {w,w}
__device__ float4 g_mwgt[BD*HD*KK*WD];        // bilinear weights (validity folded)
__device__ int4   g_midx[BD*HD*KK*WD];        // tap indices, pre-multiplied by 64

typedef unsigned long long ull;

__device__ __forceinline__ void fma2(ull &acc, ull a, ull b) {
    asm("fma.rn.f32x2 %0, %1, %2, %0;" : "+l"(acc) : "l"(a), "l"(b));
}
__device__ __forceinline__ ull pack2(float a, float b) {
    ull r; asm("mov.b64 %0, {%1, %2};" : "=l"(r) : "f"(a), "f"(b)); return r;
}
__device__ __forceinline__ float2 unpack2(ull v) {
    float2 r; asm("mov.b64 {%0, %1}, %2;" : "=f"(r.x), "=f"(r.y) : "l"(v)); return r;
}

// ------------------------- kernel 1: NCHW -> NHWC ---------------------------
__global__ __launch_bounds__(256)
void k_tr(const float* __restrict__ x) {
    __shared__ float tile[64][65];
    int b = blockIdx.y, hw0 = blockIdx.x * 64, t = threadIdx.x;
    const float* xb = x + (size_t)b * CIN * HW;
    #pragma unroll
    for (int it = 0; it < 16; ++it) {
        int id = t + it * 256;
        int c = id >> 6, i = id & 63;
        tile[c][i] = xb[c * HW + hw0 + i];
    }
    __syncthreads();
    float* ob = g_xhwc + (size_t)b * HW * CIN + (size_t)hw0 * CIN;
    #pragma unroll
    for (int it = 0; it < 16; ++it) {
        int id = t + it * 256;
        int i = id >> 6, c = id & 63;
        ob[id] = tile[c][i];
    }
}

// --------------------- kernel 1b: prepack w_def -----------------------------
__global__ void k_prep_w(const float* __restrict__ w_def) {
    int id = blockIdx.x * 256 + threadIdx.x;      // 0 .. 36863
    if (id >= CIN * KK * COUT) return;
    int o  = id & 63;
    int ck = id >> 6;                              // c*9 + k
    int c  = ck / 9, k = ck - c * 9;
    float w = w_def[(o * CIN + c) * KK + k];
    g_wd2[id] = make_float2(w, w);
}

// ------------- kernel 2: offset conv + bilinear metadata --------------------
// grid (HD, BD), 128 threads (thread = w)
__global__ __launch_bounds__(128)
void k_off(const float* __restrict__ x, const float* __restrict__ w_off,
           const float* __restrict__ b_off) {
    __shared__ ull woffp[576 * 10];   // [tap][c] groups of 9 paired weights, padded to 10
    int h = blockIdx.x, b = blockIdx.y, t = threadIdx.x;

    for (int id = t; id < 576 * 9; id += 128) {
        int grp = id / 9, j = id - grp * 9;
        int tap = grp >> 6, c = grp & 63;
        float wa = w_off[((2 * j    ) * CIN + c) * KK + tap];
        float wb = w_off[((2 * j + 1) * CIN + c) * KK + tap];
        woffp[grp * 10 + j] = pack2(wa, wb);
    }
    __syncthreads();

    ull acc[9];
    #pragma unroll
    for (int j = 0; j < 9; ++j) acc[j] = 0ULL;   // two +0.0f

    const float* xb = x + (size_t)b * CIN * HW;
    #pragma unroll
    for (int tap = 0; tap < 9; ++tap) {
        int dy = tap / 3 - 1, dx = tap % 3 - 1;
        int hy = h + dy;
        if (hy < 0 || hy >= HD) continue;
        int wx = t + dx;
        bool vx = (wx >= 0) && (wx < WD);
        const float* xr = xb + hy * WD + wx;
        const ull* wp0 = woffp + tap * 64 * 10;
        for (int c = 0; c < 64; ++c) {
            float xv = vx ? xr[c * HW] : 0.f;
            ull xp = pack2(xv, xv);
            const ull* wp = wp0 + c * 10;
            ulonglong2 q0 = *(const ulonglong2*)(wp);
            ulonglong2 q1 = *(const ulonglong2*)(wp + 2);
            ulonglong2 q2 = *(const ulonglong2*)(wp + 4);
            ulonglong2 q3 = *(const ulonglong2*)(wp + 6);
            ull        q8 = wp[8];
            fma2(acc[0], xp, q0.x); fma2(acc[1], xp, q0.y);
            fma2(acc[2], xp, q1.x); fma2(acc[3], xp, q1.y);
            fma2(acc[4], xp, q2.x); fma2(acc[5], xp, q2.y);
            fma2(acc[6], xp, q3.x); fma2(acc[7], xp, q3.y);
            fma2(acc[8], xp, q8);
        }
    }

    int base = ((b * HD + h) * KK) * WD + t;
    #pragma unroll
    for (int k = 0; k < 9; ++k) {
        float2 o2 = unpack2(acc[k]);
        float dy  = o2.x + b_off[2 * k];
        float dxo = o2.y + b_off[2 * k + 1];
        float py = (float)(h - 1 + k / 3) + dy;
        float px = (float)(t - 1 + k % 3) + dxo;
        float y0f = floorf(py), x0f = floorf(px);
        float fy = py - y0f, fx = px - x0f;
        int y0 = (int)y0f, x0 = (int)x0f;
        int y1 = y0 + 1, x1 = x0 + 1;
        float vy0 = (y0 >= 0 && y0 < HD) ? 1.f : 0.f;
        float vy1 = (y1 >= 0 && y1 < HD) ? 1.f : 0.f;
        float vx0 = (x0 >= 0 && x0 < WD) ? 1.f : 0.f;
        float vx1 = (x1 >= 0 && x1 < WD) ? 1.f : 0.f;
        float w00 = (1.f - fy) * (1.f - fx) * vy0 * vx0;
        float w01 = (1.f - fy) * fx         * vy0 * vx1;
        float w10 = fy * (1.f - fx)         * vy1 * vx0;
        float w11 = fy * fx                 * vy1 * vx1;
        int cy0 = min(max(y0, 0), HD - 1), cy1 = min(max(y1, 0), HD - 1);
        int cx0 = min(max(x0, 0), WD - 1), cx1 = min(max(x1, 0), WD - 1);
        g_mwgt[base + k * WD] = make_float4(w00, w01, w10, w11);
        g_midx[base + k * WD] = make_int4((cy0 * WD + cx0) * CIN,
                                          (cy0 * WD + cx1) * CIN,
                                          (cy1 * WD + cx0) * CIN,
                                          (cy1 * WD + cx1) * CIN);
    }
}

// ---------------- kernel 3: sample + 64x576 GEMM per pixel ------------------
// grid (HD, BD) = one row of 128 pixels per CTA, 256 threads
#define S_STRIDE 132                         // 128 + 4 pad -> 16B aligned, conflict-free
#define SMEM_MWGT 0
#define SMEM_MIDX 18432
#define SMEM_S    36864
#define SMEM_W2   74880
#define SMEM_MAIN 111744

__global__ __launch_bounds__(256, 2)
void k_main(float* __restrict__ out) {
    extern __shared__ char smem[];
    float4* mwgt = (float4*)(smem + SMEM_MWGT);
    int4*   midx = (int4*)  (smem + SMEM_MIDX);
    float*  S    = (float*) (smem + SMEM_S);     // [72][132]
    float2* W2   = (float2*)(smem + SMEM_W2);    // [72][64] {w,w}

    int h = blockIdx.x, b = blockIdx.y, t = threadIdx.x;

    int mbase = (b * HD + h) * KK * WD;
    for (int id = t; id < KK * WD; id += 256) {
        mwgt[id] = g_mwgt[mbase + id];
        midx[id] = g_midx[mbase + id];
    }
    __syncthreads();

    ull acc01[8], acc23[8];
    #pragma unroll
    for (int o = 0; o < 8; ++o) { acc01[o] = 0ULL; acc23[o] = 0ULL; }

    int c  = t & 7,  g  = t >> 3;    // stage-1 mapping: 8-lane channel groups
    int pg = t & 31, og = t >> 5;    // stage-2 mapping: 32 pixel-groups x 8 out-groups
    const float* xb = g_xhwc + (size_t)b * HW * CIN;

    for (int cc = 0; cc < 8; ++cc) {
        // weights slice for this 8-channel chunk (coalesced, L2-resident)
        const float2* wsrc = g_wd2 + cc * 8 * KK * COUT;
        for (int id = t; id < 72 * 64; id += 256) W2[id] = wsrc[id];

        // gather S[(c_local*9+k)][p]
        const float* xc = xb + cc * 8 + c;
        #pragma unroll 4
        for (int it = 0; it < 36; ++it) {
            int pi = it * 32 + g;               // k*128 + p
            float4 wg = mwgt[pi];
            int4   ii = midx[pi];
            int k = pi >> 7, p = pi & 127;
            float s = wg.x * xc[ii.x] + wg.y * xc[ii.y]
                    + wg.z * xc[ii.z] + wg.w * xc[ii.w];
            S[(c * KK + k) * S_STRIDE + p] = s;
        }
        __syncthreads();

        // register-blocked GEMM over the 72 (c,k) rows of this chunk
        #pragma unroll 8
        for (int row = 0; row < 72; ++row) {
            ulonglong2 sv = *(const ulonglong2*)(S + row * S_STRIDE + pg * 4);
            const ulonglong2* wp = (const ulonglong2*)(W2 + row * 64 + og * 8);
            ulonglong2 wa = wp[0], wb2 = wp[1], wc2 = wp[2], wd2 = wp[3];
            fma2(acc01[0], sv.x, wa.x);  fma2(acc23[0], sv.y, wa.x);
            fma2(acc01[1], sv.x, wa.y);  fma2(acc23[1], sv.y, wa.y);
            fma2(acc01[2], sv.x, wb2.x); fma2(acc23[2], sv.y, wb2.x);
            fma2(acc01[3], sv.x, wb2.y); fma2(acc23[3], sv.y, wb2.y);
            fma2(acc01[4], sv.x, wc2.x); fma2(acc23[4], sv.y, wc2.x);
            fma2(acc01[5], sv.x, wc2.y); fma2(acc23[5], sv.y, wc2.y);
            fma2(acc01[6], sv.x, wd2.x); fma2(acc23[6], sv.y, wd2.x);
            fma2(acc01[7], sv.x, wd2.y); fma2(acc23[7], sv.y, wd2.y);
        }
        __syncthreads();
    }

    // epilogue: out[b][og*8+o][h][pg*4 .. +3]
    float* op = out + (((size_t)(b * COUT + og * 8) * HD + h) * WD) + pg * 4;
    #pragma unroll
    for (int o = 0; o < 8; ++o) {
        float2 a = unpack2(acc01[o]);
        float2 q = unpack2(acc23[o]);
        *(float4*)(op + (size_t)o * HW) = make_float4(a.x, a.y, q.x, q.y);
    }
}

// ------------------------------- launch -------------------------------------
extern "C" void kernel_launch(void* const* d_in, const int* in_sizes, int n_in,
                              void* d_out, int out_size) {
    const float* x     = (const float*)d_in[0];
    const float* w_off = (const float*)d_in[1];
    const float* b_off = (const float*)d_in[2];
    const float* w_def = (const float*)d_in[3];
    float* out = (float*)d_out;

    cudaFuncSetAttribute(k_main, cudaFuncAttributeMaxDynamicSharedMemorySize, SMEM_MAIN);

    k_tr    <<<dim3(HW / 64, BD), 256>>>(x);
    k_prep_w<<<(CIN * KK * COUT + 255) / 256, 256>>>(w_def);
    k_off   <<<dim3(HD, BD), 128>>>(x, w_off, b_off);
    k_main  <<<dim3(HD, BD), 256, SMEM_MAIN>>>(out);
}

// round 6
// speedup vs baseline: 1.2135x; 1.2135x over previous
#include <cuda_runtime.h>
#include <cstdint>

#define CIN   64
#define COUT  64
#define HD    128
#define WD    128
#define BD    4
#define KK    9
#define HW    (HD*WD)

// ------------------------- scratch (device globals) -------------------------
__device__ float  g_xhwc[BD*HW*CIN];          // x in NHWC (16 MB)
__device__ float  g_wd1 [CIN*KK*COUT];        // w_def [c*9+k][o] plain floats
__device__ float4 g_mwgt[BD*HD*KK*WD];        // bilinear weights (validity folded)
__device__ int4   g_midx[BD*HD*KK*WD];        // tap indices, pre-multiplied by 64
__device__ unsigned long long g_woffp[576*9]; // w_off prepacked [tap*64+c][j] {wy,wx}

typedef unsigned long long ull;

__device__ __forceinline__ void fma2(ull &acc, ull a, ull b) {
    asm("fma.rn.f32x2 %0, %1, %2, %0;" : "+l"(acc) : "l"(a), "l"(b));
}
__device__ __forceinline__ ull pack2(float a, float b) {
    ull r; asm("mov.b64 %0, {%1, %2};" : "=l"(r) : "f"(a), "f"(b)); return r;
}
__device__ __forceinline__ float2 unpack2(ull v) {
    float2 r; asm("mov.b64 {%0, %1}, %2;" : "=f"(r.x), "=f"(r.y) : "l"(v)); return r;
}

// ------------------------- kernel: NCHW -> NHWC -----------------------------
__global__ __launch_bounds__(256)
void k_tr(const float* __restrict__ x) {
    __shared__ float tile[64][65];
    int b = blockIdx.y, hw0 = blockIdx.x * 64, t = threadIdx.x;
    const float* xb = x + (size_t)b * CIN * HW;
    #pragma unroll
    for (int it = 0; it < 16; ++it) {
        int id = t + it * 256;
        int c = id >> 6, i = id & 63;
        tile[c][i] = xb[c * HW + hw0 + i];
    }
    __syncthreads();
    float* ob = g_xhwc + (size_t)b * HW * CIN + (size_t)hw0 * CIN;
    #pragma unroll
    for (int it = 0; it < 16; ++it) {
        int id = t + it * 256;
        int i = id >> 6, c = id & 63;
        ob[id] = tile[c][i];
    }
}

// --------------------- prepack w_def (plain, [c*9+k][o]) --------------------
__global__ void k_prep_w(const float* __restrict__ w_def) {
    int id = blockIdx.x * 256 + threadIdx.x;      // 0 .. 36863
    if (id >= CIN * KK * COUT) return;
    int o  = id & 63;
    int ck = id >> 6;                              // c*9 + k
    int c  = ck / 9, k = ck - c * 9;
    g_wd1[id] = w_def[(o * CIN + c) * KK + k];
}

// --------------------- prepack w_off (paired {wy,wx}) -----------------------
__global__ void k_prep_off(const float* __restrict__ w_off) {
    int id = blockIdx.x * 256 + threadIdx.x;      // 0 .. 5183
    if (id >= 576 * 9) return;
    int grp = id / 9, j = id - grp * 9;
    int tap = grp >> 6, c = grp & 63;
    float wa = w_off[((2 * j    ) * CIN + c) * KK + tap];
    float wb = w_off[((2 * j + 1) * CIN + c) * KK + tap];
    g_woffp[id] = pack2(wa, wb);
}

// ------------- kernel: offset conv + bilinear metadata ----------------------
// grid (HD, BD), 128 threads (thread = w)
__global__ __launch_bounds__(128)
void k_off(const float* __restrict__ x, const float* __restrict__ b_off) {
    __shared__ ull woffp[576 * 10];   // [tap*64+c][j], padded to 10
    int h = blockIdx.x, b = blockIdx.y, t = threadIdx.x;

    for (int id = t; id < 576 * 9; id += 128) {
        int grp = id / 9, j = id - grp * 9;
        woffp[grp * 10 + j] = g_woffp[id];
    }
    __syncthreads();

    ull acc[9];
    #pragma unroll
    for (int j = 0; j < 9; ++j) acc[j] = 0ULL;

    const float* xb = x + (size_t)b * CIN * HW;
    #pragma unroll
    for (int tap = 0; tap < 9; ++tap) {
        int dy = tap / 3 - 1, dx = tap % 3 - 1;
        int hy = h + dy;
        if (hy < 0 || hy >= HD) continue;
        int wx = t + dx;
        bool vx = (wx >= 0) && (wx < WD);
        const float* xr = xb + hy * WD + wx;
        const ull* wp0 = woffp + tap * 64 * 10;
        for (int c = 0; c < 64; ++c) {
            float xv = vx ? xr[c * HW] : 0.f;
            ull xp = pack2(xv, xv);
            const ull* wp = wp0 + c * 10;
            ulonglong2 q0 = *(const ulonglong2*)(wp);
            ulonglong2 q1 = *(const ulonglong2*)(wp + 2);
            ulonglong2 q2 = *(const ulonglong2*)(wp + 4);
            ulonglong2 q3 = *(const ulonglong2*)(wp + 6);
            ull        q8 = wp[8];
            fma2(acc[0], xp, q0.x); fma2(acc[1], xp, q0.y);
            fma2(acc[2], xp, q1.x); fma2(acc[3], xp, q1.y);
            fma2(acc[4], xp, q2.x); fma2(acc[5], xp, q2.y);
            fma2(acc[6], xp, q3.x); fma2(acc[7], xp, q3.y);
            fma2(acc[8], xp, q8);
        }
    }

    int base = ((b * HD + h) * KK) * WD + t;
    #pragma unroll
    for (int k = 0; k < 9; ++k) {
        float2 o2 = unpack2(acc[k]);
        float dy  = o2.x + b_off[2 * k];
        float dxo = o2.y + b_off[2 * k + 1];
        float py = (float)(h - 1 + k / 3) + dy;
        float px = (float)(t - 1 + k % 3) + dxo;
        float y0f = floorf(py), x0f = floorf(px);
        float fy = py - y0f, fx = px - x0f;
        int y0 = (int)y0f, x0 = (int)x0f;
        int y1 = y0 + 1, x1 = x0 + 1;
        float vy0 = (y0 >= 0 && y0 < HD) ? 1.f : 0.f;
        float vy1 = (y1 >= 0 && y1 < HD) ? 1.f : 0.f;
        float vx0 = (x0 >= 0 && x0 < WD) ? 1.f : 0.f;
        float vx1 = (x1 >= 0 && x1 < WD) ? 1.f : 0.f;
        float w00 = (1.f - fy) * (1.f - fx) * vy0 * vx0;
        float w01 = (1.f - fy) * fx         * vy0 * vx1;
        float w10 = fy * (1.f - fx)         * vy1 * vx0;
        float w11 = fy * fx                 * vy1 * vx1;
        int cy0 = min(max(y0, 0), HD - 1), cy1 = min(max(y1, 0), HD - 1);
        int cx0 = min(max(x0, 0), WD - 1), cx1 = min(max(x1, 0), WD - 1);
        g_mwgt[base + k * WD] = make_float4(w00, w01, w10, w11);
        g_midx[base + k * WD] = make_int4((cy0 * WD + cx0) * CIN,
                                          (cy0 * WD + cx1) * CIN,
                                          (cy1 * WD + cx0) * CIN,
                                          (cy1 * WD + cx1) * CIN);
    }
}

// ---------------- main: sample + 64x576 GEMM per pixel ----------------------
// grid (HD, BD) = one row of 128 px per CTA, 128 threads, thread = 8px x 8out
#define SROW  132                      // S row stride (floats): conflict-free
#define WROW  96                       // W row stride: 8 groups of (8 + 4 pad)
#define S_FLOATS (72 * SROW)           // 9504
#define SMEM_MAIN ((S_FLOATS + 72 * WROW) * 4)   // 65,664 B -> 3 CTAs/SM

__global__ __launch_bounds__(128, 3)
void k_main(float* __restrict__ out) {
    extern __shared__ float smem[];
    float* S  = smem;                  // [72][132]
    float* W1 = smem + S_FLOATS;       // [72][96] (8 valid + 4 pad per og group)

    int h = blockIdx.x, b = blockIdx.y, t = threadIdx.x;

    int c2 = t & 3,  g  = t >> 2;      // gather map: 4 channel-pairs x 32 task groups
    int og = t & 7,  pg = t >> 3;      // gemm map:   8 out-groups  x 16 px-groups

    ull acc[4][8];
    #pragma unroll
    for (int i = 0; i < 4; ++i)
        #pragma unroll
        for (int o = 0; o < 8; ++o) acc[i][o] = 0ULL;

    const float* xb = g_xhwc + (size_t)b * HW * CIN;
    int mbase = (b * HD + h) * KK * WD;
    const float4* mw = g_mwgt + mbase;
    const int4*   mi = g_midx + mbase;

    for (int cc = 0; cc < 8; ++cc) {
        // ---- stage weights for this 8-channel chunk (coalesced, L2 hit) ----
        const float* wsrc = g_wd1 + cc * 72 * 64;
        #pragma unroll
        for (int i = 0; i < 36; ++i) {
            int id = t + i * 128;
            int row = id >> 6, o = id & 63;
            W1[row * WROW + (o >> 3) * 12 + (o & 7)] = wsrc[id];
        }

        // ---- gather S[(c*9+k)][p], 2 channels per lane via float2 ----------
        const float* xc = xb + cc * 8 + c2 * 2;
        #pragma unroll 4
        for (int it = 0; it < 36; ++it) {
            int pi = it * 32 + g;                  // k*128 + p
            float4 wg = mw[pi];
            int4   ii = mi[pi];
            ull v0 = *(const ull*)(xc + ii.x);
            ull v1 = *(const ull*)(xc + ii.y);
            ull v2 = *(const ull*)(xc + ii.z);
            ull v3 = *(const ull*)(xc + ii.w);
            ull s = 0ULL;
            fma2(s, v0, pack2(wg.x, wg.x));
            fma2(s, v1, pack2(wg.y, wg.y));
            fma2(s, v2, pack2(wg.z, wg.z));
            fma2(s, v3, pack2(wg.w, wg.w));
            float2 sv = unpack2(s);
            int k = pi >> 7, p = pi & 127;
            int r0 = (c2 * 2) * KK + k;
            S[r0 * SROW + p]        = sv.x;
            S[(r0 + KK) * SROW + p] = sv.y;
        }
        __syncthreads();

        // ---- register-blocked GEMM: 72 rows, 8px x 8out per thread ---------
        const float* srow = S + pg * 8;
        const float* wrow = W1 + og * 12;
        #pragma unroll 2
        for (int row = 0; row < 72; ++row) {
            ulonglong2 s01 = *(const ulonglong2*)(srow + row * SROW);
            ulonglong2 s23 = *(const ulonglong2*)(srow + row * SROW + 4);
            float4 wa = *(const float4*)(wrow + row * WROW);
            float4 wb = *(const float4*)(wrow + row * WROW + 4);
            ull w0 = pack2(wa.x, wa.x), w1 = pack2(wa.y, wa.y);
            ull w2 = pack2(wa.z, wa.z), w3 = pack2(wa.w, wa.w);
            ull w4 = pack2(wb.x, wb.x), w5 = pack2(wb.y, wb.y);
            ull w6 = pack2(wb.z, wb.z), w7 = pack2(wb.w, wb.w);
            fma2(acc[0][0], s01.x, w0); fma2(acc[1][0], s01.y, w0);
            fma2(acc[2][0], s23.x, w0); fma2(acc[3][0], s23.y, w0);
            fma2(acc[0][1], s01.x, w1); fma2(acc[1][1], s01.y, w1);
            fma2(acc[2][1], s23.x, w1); fma2(acc[3][1], s23.y, w1);
            fma2(acc[0][2], s01.x, w2); fma2(acc[1][2], s01.y, w2);
            fma2(acc[2][2], s23.x, w2); fma2(acc[3][2], s23.y, w2);
            fma2(acc[0][3], s01.x, w3); fma2(acc[1][3], s01.y, w3);
            fma2(acc[2][3], s23.x, w3); fma2(acc[3][3], s23.y, w3);
            fma2(acc[0][4], s01.x, w4); fma2(acc[1][4], s01.y, w4);
            fma2(acc[2][4], s23.x, w4); fma2(acc[3][4], s23.y, w4);
            fma2(acc[0][5], s01.x, w5); fma2(acc[1][5], s01.y, w5);
            fma2(acc[2][5], s23.x, w5); fma2(acc[3][5], s23.y, w5);
            fma2(acc[0][6], s01.x, w6); fma2(acc[1][6], s01.y, w6);
            fma2(acc[2][6], s23.x, w6); fma2(acc[3][6], s23.y, w6);
            fma2(acc[0][7], s01.x, w7); fma2(acc[1][7], s01.y, w7);
            fma2(acc[2][7], s23.x, w7); fma2(acc[3][7], s23.y, w7);
        }
        __syncthreads();
    }

    // ---- epilogue: out[b][og*8+o][h][pg*8 .. +7] ----------------------------
    float* op = out + (((size_t)(b * COUT + og * 8) * HD + h) * WD) + pg * 8;
    #pragma unroll
    for (int o = 0; o < 8; ++o) {
        float2 a0 = unpack2(acc[0][o]);
        float2 a1 = unpack2(acc[1][o]);
        float2 a2 = unpack2(acc[2][o]);
        float2 a3 = unpack2(acc[3][o]);
        *(float4*)(op + (size_t)o * HW)     = make_float4(a0.x, a0.y, a1.x, a1.y);
        *(float4*)(op + (size_t)o * HW + 4) = make_float4(a2.x, a2.y, a3.x, a3.y);
    }
}

// ------------------------------- launch -------------------------------------
extern "C" void kernel_launch(void* const* d_in, const int* in_sizes, int n_in,
                              void* d_out, int out_size) {
    const float* x     = (const float*)d_in[0];
    const float* w_off = (const float*)d_in[1];
    const float* b_off = (const float*)d_in[2];
    const float* w_def = (const float*)d_in[3];
    float* out = (float*)d_out;

    cudaFuncSetAttribute(k_main, cudaFuncAttributeMaxDynamicSharedMemorySize, SMEM_MAIN);

    k_tr      <<<dim3(HW / 64, BD), 256>>>(x);
    k_prep_w  <<<(CIN * KK * COUT + 255) / 256, 256>>>(w_def);
    k_prep_off<<<(576 * 9 + 255) / 256, 256>>>(w_off);
    k_off     <<<dim3(HD, BD), 128>>>(x, b_off);
    k_main    <<<dim3(HD, BD), 128, SMEM_MAIN>>>(out);
}